// round 11
// baseline (speedup 1.0000x reference)
#include <cuda_runtime.h>
#include <cstdint>

// Problem constants
constexpr int Bq = 8, Tq = 1024, Dq = 512, Hq = 8, KDq = 64;
constexpr int BT = Bq * Tq;          // 8192
constexpr long long NOUT = (long long)BT * Dq;              // 4,194,304
constexpr long long NATT = (long long)Bq * Hq * Tq * Tq;    // 67,108,864

// Scratch (device globals: allocation-free rule)
__device__ float g_qh[BT * Dq];
__device__ float g_kh[BT * Dq];
__device__ float g_vh[BT * Dq];
__device__ float g_at[BT * Dq];
__device__ float g_q2[Bq * Hq * Tq];
__device__ float g_k2[Bq * Hq * Tq];

__device__ __forceinline__ unsigned f2tf(float x) {
    unsigned r;
    asm("cvt.rna.tf32.f32 %0, %1;" : "=r"(r) : "f"(x));
    return r;
}
__device__ __forceinline__ unsigned fbits(float x) { return __float_as_uint(x); }

__device__ __forceinline__ void mma_m16n8k8(float c[4], const unsigned a[4], const unsigned b[2]) {
    asm volatile(
        "mma.sync.aligned.m16n8k8.row.col.f32.tf32.tf32.f32 "
        "{%0,%1,%2,%3}, {%4,%5,%6,%7}, {%8,%9}, {%0,%1,%2,%3};"
        : "+f"(c[0]), "+f"(c[1]), "+f"(c[2]), "+f"(c[3])
        : "r"(a[0]), "r"(a[1]), "r"(a[2]), "r"(a[3]), "r"(b[0]), "r"(b[1]));
}

// ---------------------------------------------------------------------------
// K=512 GEMM: C[8192,512] = A[8192,512] @ W[512,512]   (R9 configuration)
// Block tile 128x64, 256 threads (warp grid 4x2, warp tile 32x32).
// SPLIT=3: 3xTF32 hi/lo staged in smem (cvt at store); SPLIT=1: plain tf32.
// ---------------------------------------------------------------------------
template <int SPLIT>
__global__ void __launch_bounds__(256) gemm_k512(
    const float* __restrict__ A, const float* __restrict__ W, float* __restrict__ C)
{
    __shared__ float Ah[128][36];
    __shared__ float Al[(SPLIT == 3) ? 128 : 1][36];
    __shared__ float Wh[32][72];
    __shared__ float Wl[(SPLIT == 3) ? 32 : 1][72];

    const int tid = threadIdx.x;
    const int lane = tid & 31, warp = tid >> 5;
    const int gid = lane >> 2, tig = lane & 3;
    const int wm = warp & 3, wn = warp >> 2;
    const int m0 = blockIdx.y * 128, n0 = blockIdx.x * 64;

    float acc[2][4][4] = {};

    for (int k0 = 0; k0 < 512; k0 += 32) {
#pragma unroll
        for (int i = 0; i < 4; i++) {
            int idx = tid + i * 256;        // 1024 float4 for A 128x32
            int r = idx >> 3, c = (idx & 7) << 2;
            const float4 v = *reinterpret_cast<const float4*>(A + (size_t)(m0 + r) * 512 + k0 + c);
            if (SPLIT == 3) {
                float h0 = __uint_as_float(f2tf(v.x)), h1 = __uint_as_float(f2tf(v.y));
                float h2 = __uint_as_float(f2tf(v.z)), h3 = __uint_as_float(f2tf(v.w));
                Ah[r][c] = h0; Ah[r][c + 1] = h1; Ah[r][c + 2] = h2; Ah[r][c + 3] = h3;
                Al[r][c] = v.x - h0; Al[r][c + 1] = v.y - h1;
                Al[r][c + 2] = v.z - h2; Al[r][c + 3] = v.w - h3;
            } else {
                Ah[r][c] = v.x; Ah[r][c + 1] = v.y; Ah[r][c + 2] = v.z; Ah[r][c + 3] = v.w;
            }
        }
#pragma unroll
        for (int i = 0; i < 2; i++) {
            int idx = tid + i * 256;        // 512 float4 for W 32x64
            int r = idx >> 4, c = (idx & 15) << 2;
            const float4 v = *reinterpret_cast<const float4*>(W + (size_t)(k0 + r) * 512 + n0 + c);
            if (SPLIT == 3) {
                float h0 = __uint_as_float(f2tf(v.x)), h1 = __uint_as_float(f2tf(v.y));
                float h2 = __uint_as_float(f2tf(v.z)), h3 = __uint_as_float(f2tf(v.w));
                Wh[r][c] = h0; Wh[r][c + 1] = h1; Wh[r][c + 2] = h2; Wh[r][c + 3] = h3;
                Wl[r][c] = v.x - h0; Wl[r][c + 1] = v.y - h1;
                Wl[r][c + 2] = v.z - h2; Wl[r][c + 3] = v.w - h3;
            } else {
                Wh[r][c] = v.x; Wh[r][c + 1] = v.y; Wh[r][c + 2] = v.z; Wh[r][c + 3] = v.w;
            }
        }
        __syncthreads();

#pragma unroll
        for (int s = 0; s < 4; s++) {
            const int kk = s * 8;
            unsigned ah[2][4], al[2][4];
#pragma unroll
            for (int mi = 0; mi < 2; mi++) {
                const int r0 = wm * 32 + mi * 16;
                ah[mi][0] = fbits(Ah[r0 + gid][kk + tig]);
                ah[mi][1] = fbits(Ah[r0 + gid + 8][kk + tig]);
                ah[mi][2] = fbits(Ah[r0 + gid][kk + tig + 4]);
                ah[mi][3] = fbits(Ah[r0 + gid + 8][kk + tig + 4]);
                if (SPLIT == 3) {
                    al[mi][0] = fbits(Al[r0 + gid][kk + tig]);
                    al[mi][1] = fbits(Al[r0 + gid + 8][kk + tig]);
                    al[mi][2] = fbits(Al[r0 + gid][kk + tig + 4]);
                    al[mi][3] = fbits(Al[r0 + gid + 8][kk + tig + 4]);
                }
            }
            unsigned bh[4][2], bl[4][2];
#pragma unroll
            for (int ni = 0; ni < 4; ni++) {
                const int c0 = wn * 32 + ni * 8 + gid;
                bh[ni][0] = fbits(Wh[kk + tig][c0]);
                bh[ni][1] = fbits(Wh[kk + tig + 4][c0]);
                if (SPLIT == 3) {
                    bl[ni][0] = fbits(Wl[kk + tig][c0]);
                    bl[ni][1] = fbits(Wl[kk + tig + 4][c0]);
                }
            }
#pragma unroll
            for (int mi = 0; mi < 2; mi++)
#pragma unroll
                for (int ni = 0; ni < 4; ni++) {
                    if (SPLIT == 3) {
                        mma_m16n8k8(acc[mi][ni], al[mi], bh[ni]);
                        mma_m16n8k8(acc[mi][ni], ah[mi], bl[ni]);
                    }
                    mma_m16n8k8(acc[mi][ni], ah[mi], bh[ni]);
                }
        }
        __syncthreads();
    }

#pragma unroll
    for (int mi = 0; mi < 2; mi++)
#pragma unroll
        for (int ni = 0; ni < 4; ni++) {
            const int r = m0 + wm * 32 + mi * 16 + gid;
            const int c = n0 + wn * 32 + ni * 8 + tig * 2;
            *reinterpret_cast<float2*>(C + (size_t)r * 512 + c) =
                make_float2(acc[mi][ni][0], acc[mi][ni][1]);
            *reinterpret_cast<float2*>(C + (size_t)(r + 8) * 512 + c) =
                make_float2(acc[mi][ni][2], acc[mi][ni][3]);
        }
}

// ---------------------------------------------------------------------------
__global__ void norms_kernel()
{
    int idx = blockIdx.x * 256 + threadIdx.x;
    if (idx >= BT * Hq) return;
    int row = idx >> 3, h = idx & 7;
    const float* q = g_qh + (size_t)row * 512 + h * 64;
    const float* k = g_kh + (size_t)row * 512 + h * 64;
    float sq = 0.f, sk = 0.f;
#pragma unroll
    for (int i = 0; i < 16; i++) {
        float4 a = *reinterpret_cast<const float4*>(q + i * 4);
        sq += a.x * a.x + a.y * a.y + a.z * a.z + a.w * a.w;
        float4 c = *reinterpret_cast<const float4*>(k + i * 4);
        sk += c.x * c.x + c.y * c.y + c.z * c.z + c.w * c.w;
    }
    int b = row >> 10, t = row & 1023;
    g_q2[(size_t)(b * 8 + h) * 1024 + t] = sq;
    g_k2[(size_t)(b * 8 + h) * 1024 + t] = sk;
}

// ---------------------------------------------------------------------------
// Fused attention (mma.sync tf32), q-tile = 64 rows for 2 CTAs/SM (16 warps):
//  - permuted fragment-order smem layout (LDS.64) for Q hi/lo, K hi/lo, S
//  - V row-major (scalar conflict-free reads)
//  - warp grid 4x2: warp tile 16 (m) x 32 (n)
// smem = 6 * 64*72 + 128 floats = 111,104 B  ->  2 CTAs/SM
// ---------------------------------------------------------------------------
constexpr int OQH = 0;                    // Q hi   [64][72] permuted cols
constexpr int OQL = OQH + 64 * 72;        // Q lo
constexpr int OKH = OQL + 64 * 72;        // K hi   [64][72] permuted cols
constexpr int OKL = OKH + 64 * 72;        // K lo
constexpr int OVS = OKL + 64 * 72;        // V      [64][72] row-major
constexpr int OSS = OVS + 64 * 72;        // S      [64][72] permuted cols
constexpr int OQ2 = OSS + 64 * 72;        // q2     [64]
constexpr int OK2 = OQ2 + 64;             // k2     [64]
constexpr int ATTN_SMEM = (OK2 + 64) * 4; // 111,104 bytes

__global__ void __launch_bounds__(256, 2) attn_mma(float* __restrict__ Sout)
{
    extern __shared__ float sm[];
    const int tid = threadIdx.x, lane = tid & 31, warp = tid >> 5;
    const int gid = lane >> 2, tig = lane & 3;
    const int wm = warp & 3, wn = warp >> 2;     // warp tile 16 x 32
    const int bh = blockIdx.y, b = bh >> 3, h = bh & 7;
    const int m0 = blockIdx.x * 64;

    // --- Q tile load + hi/lo split into permuted layout (once) ---
    const float* qb = g_qh + ((size_t)(b * 1024 + m0)) * 512 + h * 64;
#pragma unroll
    for (int i = 0; i < 4; i++) {
        int idx = tid + i * 256;            // 1024 float4
        int r = idx >> 4, c = (idx & 15) << 2;
        float4 v = *reinterpret_cast<const float4*>(qb + (size_t)r * 512 + c);
        float h0 = __uint_as_float(f2tf(v.x)), h1 = __uint_as_float(f2tf(v.y));
        float h2 = __uint_as_float(f2tf(v.z)), h3 = __uint_as_float(f2tf(v.w));
        int base = r * 72 + (c & ~7) + ((c >> 2) & 1);   // +2 per successive col
        float* qh = sm + OQH + base;
        qh[0] = h0; qh[2] = h1; qh[4] = h2; qh[6] = h3;
        float* ql = sm + OQL + base;
        ql[0] = v.x - h0; ql[2] = v.y - h1; ql[4] = v.z - h2; ql[6] = v.w - h3;
    }
    if (tid < 64) sm[OQ2 + tid] = g_q2[(size_t)bh * 1024 + m0 + tid];

    const float* kb0 = g_kh + ((size_t)b * 1024) * 512 + h * 64;
    const float* vb0 = g_vh + ((size_t)b * 1024) * 512 + h * 64;

    // --- prefetch key tile 0 into registers ---
    float4 kreg[4], vreg[4];
    float k2v = 0.f;
#pragma unroll
    for (int i = 0; i < 4; i++) {
        int idx = tid + i * 256;            // 1024 float4 each
        int r = idx >> 4, c = (idx & 15) << 2;
        kreg[i] = *reinterpret_cast<const float4*>(kb0 + (size_t)r * 512 + c);
        vreg[i] = *reinterpret_cast<const float4*>(vb0 + (size_t)r * 512 + c);
    }
    if (tid < 64) k2v = g_k2[(size_t)bh * 1024 + tid];

    float pacc[4][4] = {};

    for (int nt = 0; nt < 16; nt++) {
        const int n0 = nt * 64;
        __syncthreads();   // prev iter's reads of K/V/S smem done

        // ---- store prefetched K (split, permuted) / V (raw rows) / k2 ----
#pragma unroll
        for (int i = 0; i < 4; i++) {
            int idx = tid + i * 256;
            int r = idx >> 4, c = (idx & 15) << 2;
            float4 v = kreg[i];
            float h0 = __uint_as_float(f2tf(v.x)), h1 = __uint_as_float(f2tf(v.y));
            float h2 = __uint_as_float(f2tf(v.z)), h3 = __uint_as_float(f2tf(v.w));
            int base = r * 72 + (c & ~7) + ((c >> 2) & 1);
            float* kh = sm + OKH + base;
            kh[0] = h0; kh[2] = h1; kh[4] = h2; kh[6] = h3;
            float* kl = sm + OKL + base;
            kl[0] = v.x - h0; kl[2] = v.y - h1; kl[4] = v.z - h2; kl[6] = v.w - h3;
            *reinterpret_cast<float4*>(sm + OVS + r * 72 + c) = vreg[i];
        }
        if (tid < 64) sm[OK2 + tid] = k2v;
        __syncthreads();

        // ---- prefetch next tile (overlaps QK/exp/SV below) ----
        if (nt < 15) {
            const int n1 = (nt + 1) * 64;
#pragma unroll
            for (int i = 0; i < 4; i++) {
                int idx = tid + i * 256;
                int r = idx >> 4, c = (idx & 15) << 2;
                kreg[i] = *reinterpret_cast<const float4*>(
                    kb0 + (size_t)(n1 + r) * 512 + c);
                vreg[i] = *reinterpret_cast<const float4*>(
                    vb0 + (size_t)(n1 + r) * 512 + c);
            }
            if (tid < 64) k2v = g_k2[(size_t)bh * 1024 + n1 + tid];
        }

        // ---- QK^T: 3xTF32, wide LDS.64 + HMMA ----
        float sacc[4][4] = {};
#pragma unroll
        for (int s = 0; s < 8; s++) {
            const int so = s * 8 + tig * 2;
            unsigned ah[4], al[4];
            {
                const float* ab = sm + OQH + (wm * 16 + gid) * 72 + so;
                float2 u0 = *reinterpret_cast<const float2*>(ab);
                float2 u1 = *reinterpret_cast<const float2*>(ab + 8 * 72);
                ah[0] = fbits(u0.x); ah[1] = fbits(u1.x);
                ah[2] = fbits(u0.y); ah[3] = fbits(u1.y);
                const float* lb = ab + (OQL - OQH);
                float2 l0 = *reinterpret_cast<const float2*>(lb);
                float2 l1 = *reinterpret_cast<const float2*>(lb + 8 * 72);
                al[0] = fbits(l0.x); al[1] = fbits(l1.x);
                al[2] = fbits(l0.y); al[3] = fbits(l1.y);
            }
            unsigned bhf[4][2], blf[4][2];
#pragma unroll
            for (int ni = 0; ni < 4; ni++) {
                const float* kb = sm + OKH + (wn * 32 + ni * 8 + gid) * 72 + so;
                float2 w0 = *reinterpret_cast<const float2*>(kb);
                bhf[ni][0] = fbits(w0.x); bhf[ni][1] = fbits(w0.y);
                float2 w1 = *reinterpret_cast<const float2*>(kb + (OKL - OKH));
                blf[ni][0] = fbits(w1.x); blf[ni][1] = fbits(w1.y);
            }
#pragma unroll
            for (int ni = 0; ni < 4; ni++) {
                mma_m16n8k8(sacc[ni], al, bhf[ni]);
                mma_m16n8k8(sacc[ni], ah, blf[ni]);
                mma_m16n8k8(sacc[ni], ah, bhf[ni]);
            }
        }

        // ---- exp epilogue: S -> smem (permuted) + gmem (row-major) ----
#pragma unroll
        for (int ni = 0; ni < 4; ni++) {
            const int r = wm * 16 + gid;
            const int c = wn * 32 + ni * 8 + tig * 2;     // even
            float q2a = sm[OQ2 + r], q2b = sm[OQ2 + r + 8];
            float k2a = sm[OK2 + c], k2b = sm[OK2 + c + 1];
            float e00 = __expf(fmaf(2.f, sacc[ni][0], -(q2a + k2a)));
            float e01 = __expf(fmaf(2.f, sacc[ni][1], -(q2a + k2b)));
            float e10 = __expf(fmaf(2.f, sacc[ni][2], -(q2b + k2a)));
            float e11 = __expf(fmaf(2.f, sacc[ni][3], -(q2b + k2b)));
            const int cp = (c & ~7) + ((c & 3) << 1) + ((c >> 2) & 1);
            sm[OSS + r * 72 + cp] = e00;
            sm[OSS + r * 72 + cp + 2] = e01;
            sm[OSS + (r + 8) * 72 + cp] = e10;
            sm[OSS + (r + 8) * 72 + cp + 2] = e11;
            if (Sout) {
                *reinterpret_cast<float2*>(
                    Sout + ((size_t)bh * 1024 + m0 + r) * 1024 + n0 + c) = make_float2(e00, e01);
                *reinterpret_cast<float2*>(
                    Sout + ((size_t)bh * 1024 + m0 + r + 8) * 1024 + n0 + c) = make_float2(e10, e11);
            }
        }
        __syncthreads();   // Ss fully written (cross-warp) before S@V

        // ---- P += S @ V (tf32; S via LDS.64 permuted, V scalar conflict-free) ----
#pragma unroll
        for (int s = 0; s < 8; s++) {
            const int so = s * 8 + tig * 2;
            const int kk = s * 8;
            unsigned af[4];
            {
                const float* ab = sm + OSS + (wm * 16 + gid) * 72 + so;
                float2 u0 = *reinterpret_cast<const float2*>(ab);
                float2 u1 = *reinterpret_cast<const float2*>(ab + 8 * 72);
                af[0] = fbits(u0.x); af[1] = fbits(u1.x);
                af[2] = fbits(u0.y); af[3] = fbits(u1.y);
            }
            unsigned bf[4][2];
#pragma unroll
            for (int ni = 0; ni < 4; ni++) {
                const int c0 = wn * 32 + ni * 8 + gid;
                bf[ni][0] = fbits(sm[OVS + (kk + tig) * 72 + c0]);
                bf[ni][1] = fbits(sm[OVS + (kk + tig + 4) * 72 + c0]);
            }
#pragma unroll
            for (int ni = 0; ni < 4; ni++)
                mma_m16n8k8(pacc[ni], af, bf[ni]);
        }
    }

    // ---- write P tile -> g_at [B*T, H*KD] ----
#pragma unroll
    for (int ni = 0; ni < 4; ni++) {
        const int r = m0 + wm * 16 + gid;
        const int c = h * 64 + wn * 32 + ni * 8 + tig * 2;
        float* dst = g_at + (size_t)(b * 1024 + r) * 512 + c;
        *reinterpret_cast<float2*>(dst) = make_float2(pacc[ni][0], pacc[ni][1]);
        *reinterpret_cast<float2*>(dst + (size_t)8 * 512) =
            make_float2(pacc[ni][2], pacc[ni][3]);
    }
}

// ---------------------------------------------------------------------------
extern "C" void kernel_launch(void* const* d_in, const int* in_sizes, int n_in,
                              void* d_out, int out_size)
{
    const float* query = (const float*)d_in[0];
    const float* key_  = (const float*)d_in[1];
    const float* value = (const float*)d_in[2];
    const float* Wq = (const float*)d_in[3];
    const float* Wk = (const float*)d_in[4];
    const float* Wv = (const float*)d_in[5];
    const float* Wo = (const float*)d_in[6];

    float *qh, *kh, *vh, *at;
    cudaGetSymbolAddress((void**)&qh, g_qh);
    cudaGetSymbolAddress((void**)&kh, g_kh);
    cudaGetSymbolAddress((void**)&vh, g_vh);
    cudaGetSymbolAddress((void**)&at, g_at);

    // Output layout: reference returns (out, attn_weights), flattened in order.
    float* outp = nullptr;
    float* attnW = nullptr;
    long long osz = (long long)out_size;
    if (osz >= NOUT + NATT) { outp = (float*)d_out; attnW = (float*)d_out + NOUT; }
    else if (osz >= NATT)   { attnW = (float*)d_out; }
    else                    { outp = (float*)d_out; }

    dim3 gg(8, 64);   // (N/64, M/128)
    gemm_k512<3><<<gg, 256>>>(query, Wq, qh);
    gemm_k512<3><<<gg, 256>>>(key_,  Wk, kh);
    gemm_k512<1><<<gg, 256>>>(value, Wv, vh);
    norms_kernel<<<(BT * Hq + 255) / 256, 256>>>();

    cudaFuncSetAttribute((const void*)attn_mma,
                         cudaFuncAttributeMaxDynamicSharedMemorySize, ATTN_SMEM);
    attn_mma<<<dim3(16, 64), 256, ATTN_SMEM>>>(attnW);

    if (outp) gemm_k512<1><<<gg, 256>>>(at, Wo, outp);
}

// round 12
// speedup vs baseline: 1.0496x; 1.0496x over previous
#include <cuda_runtime.h>
#include <cstdint>

// Problem constants
constexpr int Bq = 8, Tq = 1024, Dq = 512, Hq = 8, KDq = 64;
constexpr int BT = Bq * Tq;          // 8192
constexpr long long NOUT = (long long)BT * Dq;              // 4,194,304
constexpr long long NATT = (long long)Bq * Hq * Tq * Tq;    // 67,108,864

// Scratch (device globals: allocation-free rule)
__device__ float g_qh[BT * Dq];
__device__ float g_kh[BT * Dq];
__device__ float g_vh[BT * Dq];
__device__ float g_at[BT * Dq];
__device__ float g_at2[BT * Dq];
__device__ float g_q2[Bq * Hq * Tq];
__device__ float g_k2[Bq * Hq * Tq];

__device__ __forceinline__ unsigned f2tf(float x) {
    unsigned r;
    asm("cvt.rna.tf32.f32 %0, %1;" : "=r"(r) : "f"(x));
    return r;
}
__device__ __forceinline__ unsigned fbits(float x) { return __float_as_uint(x); }

__device__ __forceinline__ void mma_m16n8k8(float c[4], const unsigned a[4], const unsigned b[2]) {
    asm volatile(
        "mma.sync.aligned.m16n8k8.row.col.f32.tf32.tf32.f32 "
        "{%0,%1,%2,%3}, {%4,%5,%6,%7}, {%8,%9}, {%0,%1,%2,%3};"
        : "+f"(c[0]), "+f"(c[1]), "+f"(c[2]), "+f"(c[3])
        : "r"(a[0]), "r"(a[1]), "r"(a[2]), "r"(a[3]), "r"(b[0]), "r"(b[1]));
}

// ---------------------------------------------------------------------------
// K=512 GEMM: C[8192,512] = A[8192,512] @ W[512,512]   (R9 configuration)
// ADD is compile-time: QKV instantiations carry no extra code in the hot loop.
// ---------------------------------------------------------------------------
template <int SPLIT, bool ADD>
__global__ void __launch_bounds__(256) gemm_k512(
    const float* __restrict__ A, const float* __restrict__ Aadd,
    const float* __restrict__ W, float* __restrict__ C)
{
    __shared__ float Ah[128][36];
    __shared__ float Al[(SPLIT == 3) ? 128 : 1][36];
    __shared__ float Wh[32][72];
    __shared__ float Wl[(SPLIT == 3) ? 32 : 1][72];

    const int tid = threadIdx.x;
    const int lane = tid & 31, warp = tid >> 5;
    const int gid = lane >> 2, tig = lane & 3;
    const int wm = warp & 3, wn = warp >> 2;
    const int m0 = blockIdx.y * 128, n0 = blockIdx.x * 64;

    float acc[2][4][4] = {};

    for (int k0 = 0; k0 < 512; k0 += 32) {
#pragma unroll
        for (int i = 0; i < 4; i++) {
            int idx = tid + i * 256;        // 1024 float4 for A 128x32
            int r = idx >> 3, c = (idx & 7) << 2;
            float4 v = *reinterpret_cast<const float4*>(A + (size_t)(m0 + r) * 512 + k0 + c);
            if (ADD) {
                const float4 w = *reinterpret_cast<const float4*>(
                    Aadd + (size_t)(m0 + r) * 512 + k0 + c);
                v.x += w.x; v.y += w.y; v.z += w.z; v.w += w.w;
            }
            if (SPLIT == 3) {
                float h0 = __uint_as_float(f2tf(v.x)), h1 = __uint_as_float(f2tf(v.y));
                float h2 = __uint_as_float(f2tf(v.z)), h3 = __uint_as_float(f2tf(v.w));
                Ah[r][c] = h0; Ah[r][c + 1] = h1; Ah[r][c + 2] = h2; Ah[r][c + 3] = h3;
                Al[r][c] = v.x - h0; Al[r][c + 1] = v.y - h1;
                Al[r][c + 2] = v.z - h2; Al[r][c + 3] = v.w - h3;
            } else {
                Ah[r][c] = v.x; Ah[r][c + 1] = v.y; Ah[r][c + 2] = v.z; Ah[r][c + 3] = v.w;
            }
        }
#pragma unroll
        for (int i = 0; i < 2; i++) {
            int idx = tid + i * 256;        // 512 float4 for W 32x64
            int r = idx >> 4, c = (idx & 15) << 2;
            const float4 v = *reinterpret_cast<const float4*>(W + (size_t)(k0 + r) * 512 + n0 + c);
            if (SPLIT == 3) {
                float h0 = __uint_as_float(f2tf(v.x)), h1 = __uint_as_float(f2tf(v.y));
                float h2 = __uint_as_float(f2tf(v.z)), h3 = __uint_as_float(f2tf(v.w));
                Wh[r][c] = h0; Wh[r][c + 1] = h1; Wh[r][c + 2] = h2; Wh[r][c + 3] = h3;
                Wl[r][c] = v.x - h0; Wl[r][c + 1] = v.y - h1;
                Wl[r][c + 2] = v.z - h2; Wl[r][c + 3] = v.w - h3;
            } else {
                Wh[r][c] = v.x; Wh[r][c + 1] = v.y; Wh[r][c + 2] = v.z; Wh[r][c + 3] = v.w;
            }
        }
        __syncthreads();

#pragma unroll
        for (int s = 0; s < 4; s++) {
            const int kk = s * 8;
            unsigned ah[2][4], al[2][4];
#pragma unroll
            for (int mi = 0; mi < 2; mi++) {
                const int r0 = wm * 32 + mi * 16;
                ah[mi][0] = fbits(Ah[r0 + gid][kk + tig]);
                ah[mi][1] = fbits(Ah[r0 + gid + 8][kk + tig]);
                ah[mi][2] = fbits(Ah[r0 + gid][kk + tig + 4]);
                ah[mi][3] = fbits(Ah[r0 + gid + 8][kk + tig + 4]);
                if (SPLIT == 3) {
                    al[mi][0] = fbits(Al[r0 + gid][kk + tig]);
                    al[mi][1] = fbits(Al[r0 + gid + 8][kk + tig]);
                    al[mi][2] = fbits(Al[r0 + gid][kk + tig + 4]);
                    al[mi][3] = fbits(Al[r0 + gid + 8][kk + tig + 4]);
                }
            }
            unsigned bh[4][2], bl[4][2];
#pragma unroll
            for (int ni = 0; ni < 4; ni++) {
                const int c0 = wn * 32 + ni * 8 + gid;
                bh[ni][0] = fbits(Wh[kk + tig][c0]);
                bh[ni][1] = fbits(Wh[kk + tig + 4][c0]);
                if (SPLIT == 3) {
                    bl[ni][0] = fbits(Wl[kk + tig][c0]);
                    bl[ni][1] = fbits(Wl[kk + tig + 4][c0]);
                }
            }
#pragma unroll
            for (int mi = 0; mi < 2; mi++)
#pragma unroll
                for (int ni = 0; ni < 4; ni++) {
                    if (SPLIT == 3) {
                        mma_m16n8k8(acc[mi][ni], al[mi], bh[ni]);
                        mma_m16n8k8(acc[mi][ni], ah[mi], bl[ni]);
                    }
                    mma_m16n8k8(acc[mi][ni], ah[mi], bh[ni]);
                }
        }
        __syncthreads();
    }

#pragma unroll
    for (int mi = 0; mi < 2; mi++)
#pragma unroll
        for (int ni = 0; ni < 4; ni++) {
            const int r = m0 + wm * 32 + mi * 16 + gid;
            const int c = n0 + wn * 32 + ni * 8 + tig * 2;
            *reinterpret_cast<float2*>(C + (size_t)r * 512 + c) =
                make_float2(acc[mi][ni][0], acc[mi][ni][1]);
            *reinterpret_cast<float2*>(C + (size_t)(r + 8) * 512 + c) =
                make_float2(acc[mi][ni][2], acc[mi][ni][3]);
        }
}

// ---------------------------------------------------------------------------
__global__ void norms_kernel()
{
    int idx = blockIdx.x * 256 + threadIdx.x;
    if (idx >= BT * Hq) return;
    int row = idx >> 3, h = idx & 7;
    const float* q = g_qh + (size_t)row * 512 + h * 64;
    const float* k = g_kh + (size_t)row * 512 + h * 64;
    float sq = 0.f, sk = 0.f;
#pragma unroll
    for (int i = 0; i < 16; i++) {
        float4 a = *reinterpret_cast<const float4*>(q + i * 4);
        sq += a.x * a.x + a.y * a.y + a.z * a.z + a.w * a.w;
        float4 c = *reinterpret_cast<const float4*>(k + i * 4);
        sk += c.x * c.x + c.y * c.y + c.z * c.z + c.w * c.w;
    }
    int b = row >> 10, t = row & 1023;
    g_q2[(size_t)(b * 8 + h) * 1024 + t] = sq;
    g_k2[(size_t)(b * 8 + h) * 1024 + t] = sk;
}

// ---------------------------------------------------------------------------
// Fused attention, register-resident S (FlashAttention-2 style):
//  - warp grid 8x1 (warp tile 16 m x 64 n): each warp's S rows == its S@V
//    A-fragment rows -> S stays in registers, moved to A-fragment layout
//    with __shfl_sync within quads. NO S smem, NO mid-tile barrier.
//  - Q hi/lo + K hi/lo in permuted fragment-order layout (LDS.64), V row-major.
//  - 2 barriers per key tile (around K/V smem store) only.
//  - z=2 key-range split: partial P -> g_at / g_at2, summed by out-GEMM (ADD).
// smem = (2*128*72 + 3*64*72 + 192) * 4 = 129,792 B
// ---------------------------------------------------------------------------
constexpr int OQH = 0;                    // Q hi   [128][72] permuted cols
constexpr int OQL = OQH + 128 * 72;       // Q lo
constexpr int OKH = OQL + 128 * 72;       // K hi   [64][72] permuted cols
constexpr int OKL = OKH + 64 * 72;        // K lo
constexpr int OVS = OKL + 64 * 72;        // V      [64][72] row-major
constexpr int OQ2 = OVS + 64 * 72;        // q2     [128]
constexpr int OK2 = OQ2 + 128;            // k2     [64]
constexpr int ATTN_SMEM = (OK2 + 64) * 4; // 129,792 bytes

__global__ void __launch_bounds__(256) attn_mma(float* __restrict__ Sout)
{
    extern __shared__ float sm[];
    const int tid = threadIdx.x, lane = tid & 31, warp = tid >> 5;
    const int gid = lane >> 2, tig = lane & 3;
    const int wm = warp;                       // 8 warps, all in m
    const int bh = blockIdx.y, b = bh >> 3, h = bh & 7;
    const int m0 = blockIdx.x * 128;
    const int z = blockIdx.z;

    // --- Q tile load + hi/lo split into permuted layout (once) ---
    const float* qb = g_qh + ((size_t)(b * 1024 + m0)) * 512 + h * 64;
#pragma unroll
    for (int i = 0; i < 8; i++) {
        int idx = tid + i * 256;            // 2048 float4
        int r = idx >> 4, c = (idx & 15) << 2;
        float4 v = *reinterpret_cast<const float4*>(qb + (size_t)r * 512 + c);
        float h0 = __uint_as_float(f2tf(v.x)), h1 = __uint_as_float(f2tf(v.y));
        float h2 = __uint_as_float(f2tf(v.z)), h3 = __uint_as_float(f2tf(v.w));
        int base = r * 72 + (c & ~7) + ((c >> 2) & 1);   // +2 per successive col
        float* qh = sm + OQH + base;
        qh[0] = h0; qh[2] = h1; qh[4] = h2; qh[6] = h3;
        float* ql = sm + OQL + base;
        ql[0] = v.x - h0; ql[2] = v.y - h1; ql[4] = v.z - h2; ql[6] = v.w - h3;
    }
    if (tid < 128) sm[OQ2 + tid] = g_q2[(size_t)bh * 1024 + m0 + tid];

    const float* kb0 = g_kh + ((size_t)b * 1024) * 512 + h * 64;
    const float* vb0 = g_vh + ((size_t)b * 1024) * 512 + h * 64;

    // --- prefetch first key tile of this half ---
    float4 kreg[4], vreg[4];
    float k2v = 0.f;
    {
        const int nb = z * 8 * 64;
#pragma unroll
        for (int i = 0; i < 4; i++) {
            int idx = tid + i * 256;        // 1024 float4 each
            int r = idx >> 4, c = (idx & 15) << 2;
            kreg[i] = *reinterpret_cast<const float4*>(kb0 + (size_t)(nb + r) * 512 + c);
            vreg[i] = *reinterpret_cast<const float4*>(vb0 + (size_t)(nb + r) * 512 + c);
        }
        if (tid < 64) k2v = g_k2[(size_t)bh * 1024 + nb + tid];
    }

    float pacc[8][4] = {};
    const unsigned FULL = 0xffffffffu;
    const int srcA = (lane & ~3) + (tig >> 1);
    const int srcB = srcA + 2;
    const bool odd = tig & 1;

    for (int nt = 0; nt < 8; nt++) {
        const int n0 = (z * 8 + nt) * 64;
        __syncthreads();   // prev iter's reads of K/V smem done

        // ---- store prefetched K (split, permuted) / V (raw rows) / k2 ----
#pragma unroll
        for (int i = 0; i < 4; i++) {
            int idx = tid + i * 256;
            int r = idx >> 4, c = (idx & 15) << 2;
            float4 v = kreg[i];
            float h0 = __uint_as_float(f2tf(v.x)), h1 = __uint_as_float(f2tf(v.y));
            float h2 = __uint_as_float(f2tf(v.z)), h3 = __uint_as_float(f2tf(v.w));
            int base = r * 72 + (c & ~7) + ((c >> 2) & 1);
            float* kh = sm + OKH + base;
            kh[0] = h0; kh[2] = h1; kh[4] = h2; kh[6] = h3;
            float* kl = sm + OKL + base;
            kl[0] = v.x - h0; kl[2] = v.y - h1; kl[4] = v.z - h2; kl[6] = v.w - h3;
            *reinterpret_cast<float4*>(sm + OVS + r * 72 + c) = vreg[i];
        }
        if (tid < 64) sm[OK2 + tid] = k2v;
        __syncthreads();

        // ---- prefetch next tile (overlaps everything below) ----
        if (nt < 7) {
            const int n1 = (z * 8 + nt + 1) * 64;
#pragma unroll
            for (int i = 0; i < 4; i++) {
                int idx = tid + i * 256;
                int r = idx >> 4, c = (idx & 15) << 2;
                kreg[i] = *reinterpret_cast<const float4*>(
                    kb0 + (size_t)(n1 + r) * 512 + c);
                vreg[i] = *reinterpret_cast<const float4*>(
                    vb0 + (size_t)(n1 + r) * 512 + c);
            }
            if (tid < 64) k2v = g_k2[(size_t)bh * 1024 + n1 + tid];
        }

        // ---- QK^T: 3xTF32, warp tile 16x64, e[8][4] accumulators ----
        float e[8][4] = {};
#pragma unroll
        for (int s = 0; s < 8; s++) {
            const int so = s * 8 + tig * 2;
            unsigned ah[4], al[4];
            {
                const float* ab = sm + OQH + (wm * 16 + gid) * 72 + so;
                float2 u0 = *reinterpret_cast<const float2*>(ab);
                float2 u1 = *reinterpret_cast<const float2*>(ab + 8 * 72);
                ah[0] = fbits(u0.x); ah[1] = fbits(u1.x);
                ah[2] = fbits(u0.y); ah[3] = fbits(u1.y);
                const float* lb = ab + (OQL - OQH);
                float2 l0 = *reinterpret_cast<const float2*>(lb);
                float2 l1 = *reinterpret_cast<const float2*>(lb + 8 * 72);
                al[0] = fbits(l0.x); al[1] = fbits(l1.x);
                al[2] = fbits(l0.y); al[3] = fbits(l1.y);
            }
#pragma unroll
            for (int ni = 0; ni < 8; ni++) {
                const float* kb = sm + OKH + (ni * 8 + gid) * 72 + so;
                float2 w0 = *reinterpret_cast<const float2*>(kb);
                float2 w1 = *reinterpret_cast<const float2*>(kb + (OKL - OKH));
                unsigned bhf[2] = { fbits(w0.x), fbits(w0.y) };
                unsigned blf[2] = { fbits(w1.x), fbits(w1.y) };
                mma_m16n8k8(e[ni], al, bhf);
                mma_m16n8k8(e[ni], ah, blf);
                mma_m16n8k8(e[ni], ah, bhf);
            }
        }

        // ---- exp in registers + S gmem write (no smem, no barrier) ----
        {
            const int r = wm * 16 + gid;
            const float q2a = sm[OQ2 + r], q2b = sm[OQ2 + r + 8];
#pragma unroll
            for (int ni = 0; ni < 8; ni++) {
                const int c = ni * 8 + tig * 2;
                float k2a = sm[OK2 + c], k2b = sm[OK2 + c + 1];
                e[ni][0] = __expf(fmaf(2.f, e[ni][0], -(q2a + k2a)));
                e[ni][1] = __expf(fmaf(2.f, e[ni][1], -(q2a + k2b)));
                e[ni][2] = __expf(fmaf(2.f, e[ni][2], -(q2b + k2a)));
                e[ni][3] = __expf(fmaf(2.f, e[ni][3], -(q2b + k2b)));
                if (Sout) {
                    *reinterpret_cast<float2*>(
                        Sout + ((size_t)bh * 1024 + m0 + r) * 1024 + n0 + c) =
                        make_float2(e[ni][0], e[ni][1]);
                    *reinterpret_cast<float2*>(
                        Sout + ((size_t)bh * 1024 + m0 + r + 8) * 1024 + n0 + c) =
                        make_float2(e[ni][2], e[ni][3]);
                }
            }
        }

        // ---- P += S @ V: A-frags from registers via shfl, B from V smem ----
#pragma unroll
        for (int s = 0; s < 8; s++) {
            float s00 = __shfl_sync(FULL, e[s][0], srcA);
            float s01 = __shfl_sync(FULL, e[s][1], srcA);
            float s10 = __shfl_sync(FULL, e[s][2], srcA);
            float s11 = __shfl_sync(FULL, e[s][3], srcA);
            float t00 = __shfl_sync(FULL, e[s][0], srcB);
            float t01 = __shfl_sync(FULL, e[s][1], srcB);
            float t10 = __shfl_sync(FULL, e[s][2], srcB);
            float t11 = __shfl_sync(FULL, e[s][3], srcB);
            unsigned a[4];
            a[0] = fbits(odd ? s01 : s00);
            a[1] = fbits(odd ? s11 : s10);
            a[2] = fbits(odd ? t01 : t00);
            a[3] = fbits(odd ? t11 : t10);
            const int kk = s * 8;
#pragma unroll
            for (int ni = 0; ni < 8; ni++) {
                const int c0 = ni * 8 + gid;
                unsigned bf[2];
                bf[0] = fbits(sm[OVS + (kk + tig) * 72 + c0]);
                bf[1] = fbits(sm[OVS + (kk + tig + 4) * 72 + c0]);
                mma_m16n8k8(pacc[ni], a, bf);
            }
        }
    }

    // ---- write partial P tile -> g_at / g_at2 [B*T, H*KD] ----
    float* Pd = z ? g_at2 : g_at;
    {
        const int r = m0 + wm * 16 + gid;
#pragma unroll
        for (int ni = 0; ni < 8; ni++) {
            const int c = h * 64 + ni * 8 + tig * 2;
            float* dst = Pd + (size_t)(b * 1024 + r) * 512 + c;
            *reinterpret_cast<float2*>(dst) = make_float2(pacc[ni][0], pacc[ni][1]);
            *reinterpret_cast<float2*>(dst + (size_t)8 * 512) =
                make_float2(pacc[ni][2], pacc[ni][3]);
        }
    }
}

// ---------------------------------------------------------------------------
extern "C" void kernel_launch(void* const* d_in, const int* in_sizes, int n_in,
                              void* d_out, int out_size)
{
    const float* query = (const float*)d_in[0];
    const float* key_  = (const float*)d_in[1];
    const float* value = (const float*)d_in[2];
    const float* Wq = (const float*)d_in[3];
    const float* Wk = (const float*)d_in[4];
    const float* Wv = (const float*)d_in[5];
    const float* Wo = (const float*)d_in[6];

    float *qh, *kh, *vh, *at, *at2;
    cudaGetSymbolAddress((void**)&qh,  g_qh);
    cudaGetSymbolAddress((void**)&kh,  g_kh);
    cudaGetSymbolAddress((void**)&vh,  g_vh);
    cudaGetSymbolAddress((void**)&at,  g_at);
    cudaGetSymbolAddress((void**)&at2, g_at2);

    // Output layout: reference returns (out, attn_weights), flattened in order.
    float* outp = nullptr;
    float* attnW = nullptr;
    long long osz = (long long)out_size;
    if (osz >= NOUT + NATT) { outp = (float*)d_out; attnW = (float*)d_out + NOUT; }
    else if (osz >= NATT)   { attnW = (float*)d_out; }
    else                    { outp = (float*)d_out; }

    dim3 gg(8, 64);   // (N/64, M/128)  — exact R9 projection config
    gemm_k512<3, false><<<gg, 256>>>(query, nullptr, Wq, qh);
    gemm_k512<3, false><<<gg, 256>>>(key_,  nullptr, Wk, kh);
    gemm_k512<1, false><<<gg, 256>>>(value, nullptr, Wv, vh);
    norms_kernel<<<(BT * Hq + 255) / 256, 256>>>();

    cudaFuncSetAttribute((const void*)attn_mma,
                         cudaFuncAttributeMaxDynamicSharedMemorySize, ATTN_SMEM);
    attn_mma<<<dim3(8, 64, 2), 256, ATTN_SMEM>>>(attnW);

    if (outp) gemm_k512<1, true><<<gg, 256>>>(at, at2, Wo, outp);
}